// round 15
// baseline (speedup 1.0000x reference)
#include <cuda_runtime.h>
#include <cuda_fp16.h>
#include <math.h>
#include <stdint.h>

#define B_   2
#define S_   2048
#define D_   1024
#define H_   16
#define DK_  64
#define F_   4096
#define E_   8
#define TOK  (B_*S_)
#define CAP_ROWS (TOK*2 + E_*128)

#define KC   32               // k per chunk (halves)
#define SROW 40               // padded halves per A smem row (80B)
#define TILE_AB (128*SROW*2)  // 10240 bytes: A tile 128x32
#define TILE_BB2 (32*128)     // 4096 bytes: B tile 32(k) x 64(n)
#define STG_G1 (TILE_AB + 2*TILE_BB2)  // 18432 (dual, N=64)
#define STG_G0 (TILE_AB + 1*TILE_BB2)  // 14336 (single, N=64)
#define NSTG 4

// ---------------- scratch ----------------
__device__ __align__(128) float  g_x2[TOK*D_];
__device__ __align__(128) __half g_x2h[TOK*D_];
__device__ __align__(128) float  g_q [TOK*D_];
__device__ __align__(128) float  g_k [TOK*D_];
__device__ __align__(128) float  g_v [TOK*D_];
__device__ __align__(128) __half g_ah[TOK*D_];
__device__ __align__(128) float  g_kvp[32*8*DK_*DK_];
__device__ __align__(128) float  g_kv [32*DK_*DK_];
__device__ __align__(128) float  g_ksp[32*8*DK_];
__device__ __align__(128) float  g_ks [32*DK_];
__device__ __align__(128) __half g_xgh[(size_t)CAP_ROWS*D_];
__device__ __align__(128) __half g_hh[(size_t)CAP_ROWS*F_];
__device__ __align__(128) float  g_y [(size_t)CAP_ROWS*D_];
__device__ __align__(128) __half g_wd[7*(size_t)D_*D_];
__device__ __align__(128) __half g_e1[8*(size_t)D_*F_];
__device__ __align__(128) __half g_e3[8*(size_t)D_*F_];
__device__ __align__(128) __half g_e2[8*(size_t)F_*D_];
__device__ int   g_cnt[E_];
__device__ int   g_off[E_+1];
__device__ int   g_cur[E_];
__device__ int   g_topi[TOK*2];
__device__ float g_topw[TOK*2];
__device__ int   g_row[TOK*2];

// ---------------- helpers ----------------
__device__ __forceinline__ uint32_t smem_u32(const void* p) {
    uint32_t a;
    asm("{ .reg .u64 t; cvta.to.shared.u64 t, %1; cvt.u32.u64 %0, t; }" : "=r"(a) : "l"(p));
    return a;
}
__device__ __forceinline__ float silu_gate(float a, float c) {
    return a / (1.f + expf(-a)) * c;
}
__device__ __forceinline__ float phi1(float x) { return x > 0.f ? x + 1.f : expf(x); }

__device__ __forceinline__ void cp16(uint32_t s, const void* g) {
    asm volatile("cp.async.cg.shared.global [%0], [%1], 16;" :: "r"(s), "l"(g) : "memory");
}

#define LDSM4(r, addr) \
    asm volatile("ldmatrix.sync.aligned.m8n8.x4.shared.b16 {%0,%1,%2,%3}, [%4];" \
        : "=r"((r)[0]), "=r"((r)[1]), "=r"((r)[2]), "=r"((r)[3]) : "r"(addr))
#define LDSM4T(r, addr) \
    asm volatile("ldmatrix.sync.aligned.m8n8.x4.trans.shared.b16 {%0,%1,%2,%3}, [%4];" \
        : "=r"((r)[0]), "=r"((r)[1]), "=r"((r)[2]), "=r"((r)[3]) : "r"(addr))
#define MMA_F16(c, a, b) \
    asm volatile("mma.sync.aligned.m16n8k16.row.col.f32.f16.f16.f32 " \
        "{%0,%1,%2,%3}, {%4,%5,%6,%7}, {%8,%9}, {%0,%1,%2,%3};" \
        : "+f"((c)[0]), "+f"((c)[1]), "+f"((c)[2]), "+f"((c)[3]) \
        : "r"((a)[0]), "r"((a)[1]), "r"((a)[2]), "r"((a)[3]), "r"((b)[0]), "r"((b)[1]))

// ======== unified 256-thread core: 128x64 tile ========
// DUAL=1: two B operands (2 CTA/SM). DUAL=0: one B operand (3 CTA/SM).
template<int DUAL>
__device__ __forceinline__ void ld_chunk_g(
    const __half* A, int lda, const __half* B0, const __half* B1, int ldb,
    int k0, uint32_t st, int tid)
{
    const int r = tid >> 1;
    const int c = (tid & 1) * 16;
    const __half* arow = A + (size_t)r * lda + k0 + c;
    cp16(st + (uint32_t)(r * SROW + c) * 2, arow);
    cp16(st + (uint32_t)(r * SROW + c + 8) * 2, arow + 8);
    const int brow = tid >> 3;
    const int bg = tid & 7;
    const uint32_t bso = (uint32_t)brow * 128 + (uint32_t)((bg ^ (brow & 7)) << 4);
    const size_t go = (size_t)(k0 + brow) * ldb + bg * 8;
    cp16(st + TILE_AB + bso, B0 + go);
    if (DUAL) cp16(st + TILE_AB + TILE_BB2 + bso, B1 + go);
}

template<int DUAL>
__device__ __forceinline__ void compute_chunk_g(
    uint32_t st, float (&acc0)[4][2][4], float (&acc1)[4][2][4],
    int wm, int wn, int lane)
{
    const uint32_t aoff = (uint32_t)(((lane & 7) + ((lane >> 3) & 1) * 8) * SROW + (lane >> 4) * 8) * 2;
    const uint32_t stB0 = st + TILE_AB;
    const uint32_t stB1 = st + TILE_AB + TILE_BB2;
    const uint32_t bbase = (uint32_t)lane * 128;
    const uint32_t kx = (uint32_t)(lane & 7) << 4;
    uint32_t b0[2][4], b1[2][4];
    #pragma unroll
    for (int nt = 0; nt < 2; nt++) {
        const uint32_t gy = ((uint32_t)(wn * 2 + nt) << 4) ^ kx;
        LDSM4T(b0[nt], stB0 + bbase + gy);
        if (DUAL) LDSM4T(b1[nt], stB1 + bbase + gy);
    }
    #pragma unroll
    for (int ks = 0; ks < 2; ks++) {
        uint32_t a[4][4];
        #pragma unroll
        for (int mt = 0; mt < 4; mt++) {
            uint32_t addr = st + (uint32_t)((wm * 64 + mt * 16) * SROW + ks * 16) * 2 + aoff;
            LDSM4(a[mt], addr);
        }
        #pragma unroll
        for (int mt = 0; mt < 4; mt++) {
            #pragma unroll
            for (int nt = 0; nt < 2; nt++) {
                MMA_F16(acc0[mt][nt], a[mt], (b0[nt] + 2 * ks));
                if (DUAL) MMA_F16(acc1[mt][nt], a[mt], (b1[nt] + 2 * ks));
            }
        }
    }
}

template<int DUAL>
__device__ __forceinline__ void mma_mainloop_g(
    const __half* A, int lda, const __half* B0, const __half* B1, int ldb,
    int K, uint32_t sm, float (&acc0)[4][2][4], float (&acc1)[4][2][4])
{
    const int tid = threadIdx.x;
    const int lane = tid & 31, wid = tid >> 5;
    const int wm = wid & 1, wn = wid >> 1;
    const uint32_t STAGE = DUAL ? STG_G1 : STG_G0;
    const int NC = K / KC;
    #pragma unroll
    for (int p = 0; p < NSTG - 1; p++) {
        ld_chunk_g<DUAL>(A, lda, B0, B1, ldb, p * KC, sm + (uint32_t)p * STAGE, tid);
        asm volatile("cp.async.commit_group;" ::: "memory");
    }
    for (int k = 0; k < NC; k++) {
        asm volatile("cp.async.wait_group 2;" ::: "memory");
        __syncthreads();
        if (k + NSTG - 1 < NC)
            ld_chunk_g<DUAL>(A, lda, B0, B1, ldb, (k + NSTG - 1) * KC,
                             sm + (uint32_t)((k + NSTG - 1) & (NSTG - 1)) * STAGE, tid);
        asm volatile("cp.async.commit_group;" ::: "memory");
        compute_chunk_g<DUAL>(sm + (uint32_t)(k & (NSTG - 1)) * STAGE, acc0, acc1, wm, wn, lane);
    }
}

// ---------------- GEMM kernels ----------------
#define SMEM_GATED  (NSTG*STG_G1)  // 73728
#define SMEM_SINGLE (NSTG*STG_G0)  // 57344

struct GatedArgs {
    const __half* w1[3];
    const __half* w2[3];
    const float*  b1[3];
    const float*  b2[3];
    float*        C [3];
};

// z in {0,1,2}: q(phi), k(phi), v(no phi)
__global__ void __launch_bounds__(256, 2) mm_gated_kernel(GatedArgs ga)
{
    extern __shared__ __align__(128) char smem[];
    uint32_t sm = smem_u32(smem);
    const int z = blockIdx.z;
    const int bm0 = blockIdx.x * 128, bn0 = blockIdx.y * 64;
    float acc0[4][2][4] = {}, acc1[4][2][4] = {};
    mma_mainloop_g<1>(g_x2h + (size_t)bm0 * D_, D_,
                      ga.w1[z] + bn0, ga.w2[z] + bn0, D_,
                      D_, sm, acc0, acc1);
    const float* bias1 = ga.b1[z];
    const float* bias2 = ga.b2[z];
    float* C = ga.C[z];
    const int applyPhi = (z != 2);
    const int lane = threadIdx.x & 31, wid = threadIdx.x >> 5;
    const int wm = wid & 1, wn = wid >> 1;
    const int quad = lane >> 2, tq = lane & 3;
    #pragma unroll
    for (int mt = 0; mt < 4; mt++) {
        #pragma unroll
        for (int nt = 0; nt < 2; nt++) {
            const int col = bn0 + wn * 16 + nt * 8 + tq * 2;
            const int r0 = bm0 + wm * 64 + mt * 16 + quad;
            float2 bb1 = *(const float2*)(bias1 + col);
            float2 bb2 = *(const float2*)(bias2 + col);
            float2 v;
            v.x = silu_gate(acc0[mt][nt][0] + bb1.x, acc1[mt][nt][0] + bb2.x);
            v.y = silu_gate(acc0[mt][nt][1] + bb1.y, acc1[mt][nt][1] + bb2.y);
            if (applyPhi) { v.x = phi1(v.x); v.y = phi1(v.y); }
            *(float2*)(C + (size_t)r0 * D_ + col) = v;
            v.x = silu_gate(acc0[mt][nt][2] + bb1.x, acc1[mt][nt][2] + bb2.x);
            v.y = silu_gate(acc0[mt][nt][3] + bb1.y, acc1[mt][nt][3] + bb2.y);
            if (applyPhi) { v.x = phi1(v.x); v.y = phi1(v.y); }
            *(float2*)(C + (size_t)(r0 + 8) * D_ + col) = v;
        }
    }
}

// out = attn @ wo + bo + residual  (single, N=64, 3 CTAs/SM)
__global__ void __launch_bounds__(256, 3) mm_out_kernel(
    const __half* __restrict__ w, const float* __restrict__ bias,
    const float* __restrict__ res, float* __restrict__ C)
{
    extern __shared__ __align__(128) char smem[];
    uint32_t sm = smem_u32(smem);
    const int bm0 = blockIdx.x * 128, bn0 = blockIdx.y * 64;
    float acc0[4][2][4] = {}, accd[4][2][4];
    mma_mainloop_g<0>(g_ah + (size_t)bm0 * D_, D_, w + bn0, (const __half*)0, D_,
                      D_, sm, acc0, accd);
    const int lane = threadIdx.x & 31, wid = threadIdx.x >> 5;
    const int wm = wid & 1, wn = wid >> 1;
    const int quad = lane >> 2, tq = lane & 3;
    #pragma unroll
    for (int mt = 0; mt < 4; mt++) {
        #pragma unroll
        for (int nt = 0; nt < 2; nt++) {
            const int col = bn0 + wn * 16 + nt * 8 + tq * 2;
            const int r0 = bm0 + wm * 64 + mt * 16 + quad;
            float2 bb = *(const float2*)(bias + col);
            float2 rr0 = *(const float2*)(res + (size_t)r0 * D_ + col);
            float2 rr1 = *(const float2*)(res + (size_t)(r0 + 8) * D_ + col);
            float2 v;
            v.x = acc0[mt][nt][0] + bb.x + rr0.x;
            v.y = acc0[mt][nt][1] + bb.y + rr0.y;
            *(float2*)(C + (size_t)r0 * D_ + col) = v;
            v.x = acc0[mt][nt][2] + bb.x + rr1.x;
            v.y = acc0[mt][nt][3] + bb.y + rr1.y;
            *(float2*)(C + (size_t)(r0 + 8) * D_ + col) = v;
        }
    }
}

// h = silu(xg@w1[e]+b1[e]) * (xg@w3[e]+b3[e])  (dual, N=64, 2 CTAs/SM)
__global__ void __launch_bounds__(256, 2) mm_moeh_kernel(
    const float* __restrict__ eb1, const float* __restrict__ eb3)
{
    const int bm0 = blockIdx.x * 128;
    if (bm0 >= g_off[E_]) return;
    int e = 0;
    #pragma unroll
    for (int i = 0; i < E_; i++) if (bm0 >= g_off[i + 1]) e = i + 1;
    extern __shared__ __align__(128) char smem[];
    uint32_t sm = smem_u32(smem);
    const int bn0 = blockIdx.y * 64;
    const size_t wb = (size_t)e * D_ * F_ + bn0;
    float acc0[4][2][4] = {}, acc1[4][2][4] = {};
    mma_mainloop_g<1>(g_xgh + (size_t)bm0 * D_, D_, g_e1 + wb, g_e3 + wb, F_,
                      D_, sm, acc0, acc1);
    const int lane = threadIdx.x & 31, wid = threadIdx.x >> 5;
    const int wm = wid & 1, wn = wid >> 1;
    const int quad = lane >> 2, tq = lane & 3;
    const float* b1 = eb1 + (size_t)e * F_;
    const float* b3 = eb3 + (size_t)e * F_;
    #pragma unroll
    for (int mt = 0; mt < 4; mt++) {
        #pragma unroll
        for (int nt = 0; nt < 2; nt++) {
            const int col = bn0 + wn * 16 + nt * 8 + tq * 2;
            const int r0 = bm0 + wm * 64 + mt * 16 + quad;
            float2 bb1 = *(const float2*)(b1 + col);
            float2 bb3 = *(const float2*)(b3 + col);
            float v0 = silu_gate(acc0[mt][nt][0] + bb1.x, acc1[mt][nt][0] + bb3.x);
            float v1 = silu_gate(acc0[mt][nt][1] + bb1.y, acc1[mt][nt][1] + bb3.y);
            *(__half2*)(g_hh + (size_t)r0 * F_ + col) = __floats2half2_rn(v0, v1);
            v0 = silu_gate(acc0[mt][nt][2] + bb1.x, acc1[mt][nt][2] + bb3.x);
            v1 = silu_gate(acc0[mt][nt][3] + bb1.y, acc1[mt][nt][3] + bb3.y);
            *(__half2*)(g_hh + (size_t)(r0 + 8) * F_ + col) = __floats2half2_rn(v0, v1);
        }
    }
}

// y = h @ w2[e] + b2[e]  (single, N=64, 3 CTAs/SM)
__global__ void __launch_bounds__(256, 3) mm_moey_kernel(const float* __restrict__ eb2)
{
    const int bm0 = blockIdx.x * 128;
    if (bm0 >= g_off[E_]) return;
    int e = 0;
    #pragma unroll
    for (int i = 0; i < E_; i++) if (bm0 >= g_off[i + 1]) e = i + 1;
    extern __shared__ __align__(128) char smem[];
    uint32_t sm = smem_u32(smem);
    const int bn0 = blockIdx.y * 64;
    const size_t wb = (size_t)e * F_ * D_ + bn0;
    float acc0[4][2][4] = {}, accd[4][2][4];
    mma_mainloop_g<0>(g_hh + (size_t)bm0 * F_, F_, g_e2 + wb, (const __half*)0, D_,
                      F_, sm, acc0, accd);
    const int lane = threadIdx.x & 31, wid = threadIdx.x >> 5;
    const int wm = wid & 1, wn = wid >> 1;
    const int quad = lane >> 2, tq = lane & 3;
    const float* b2 = eb2 + (size_t)e * D_;
    #pragma unroll
    for (int mt = 0; mt < 4; mt++) {
        #pragma unroll
        for (int nt = 0; nt < 2; nt++) {
            const int col = bn0 + wn * 16 + nt * 8 + tq * 2;
            const int r0 = bm0 + wm * 64 + mt * 16 + quad;
            float2 bb = *(const float2*)(b2 + col);
            float2 v;
            v.x = acc0[mt][nt][0] + bb.x;
            v.y = acc0[mt][nt][1] + bb.y;
            *(float2*)(g_y + (size_t)r0 * D_ + col) = v;
            v.x = acc0[mt][nt][2] + bb.x;
            v.y = acc0[mt][nt][3] + bb.y;
            *(float2*)(g_y + (size_t)(r0 + 8) * D_ + col) = v;
        }
    }
}

// ---------------- conversion: streaming fp32 -> fp16, 16 elems/thread ----------------
__device__ __forceinline__ void conv16(const float* S, __half* Dst, int i)
{
    #pragma unroll
    for (int h = 0; h < 2; h++) {
        float4 a = ((const float4*)S)[4 * i + 2 * h];
        float4 b = ((const float4*)S)[4 * i + 2 * h + 1];
        __half2 h0 = __floats2half2_rn(a.x, a.y);
        __half2 h1 = __floats2half2_rn(a.z, a.w);
        __half2 h2 = __floats2half2_rn(b.x, b.y);
        __half2 h3 = __floats2half2_rn(b.z, b.w);
        uint4 o;
        o.x = *(uint32_t*)&h0; o.y = *(uint32_t*)&h1;
        o.z = *(uint32_t*)&h2; o.w = *(uint32_t*)&h3;
        ((uint4*)Dst)[2 * i + h] = o;
    }
}

struct Ptr7 { const float* p[7]; };
__global__ void __launch_bounds__(256) conv7_kernel(Ptr7 src, __half* dst)
{
    const int m = blockIdx.y;
    const int n16 = (int)((size_t)D_ * D_ / 16);
    int i = blockIdx.x * 256 + threadIdx.x;
    if (i < n16) conv16(src.p[m], dst + (size_t)m * D_ * D_, i);
}

struct PtrE { const float* s[3]; __half* d[3]; };
__global__ void __launch_bounds__(256) convE3_kernel(PtrE pe, int n16)
{
    const int m = blockIdx.y;
    int i = blockIdx.x * 256 + threadIdx.x;
    if (i < n16) conv16(pe.s[m], pe.d[m], i);
}

// ---------------- non-GEMM kernels ----------------
__global__ void __launch_bounds__(256) ln_kernel(
    const float* __restrict__ x, const float* __restrict__ g, const float* __restrict__ b,
    int storeF32, int clearCnt)
{
    __shared__ float rs[256], rq[256];
    const int t = blockIdx.x, tid = threadIdx.x;
    if (clearCnt && t == 0 && tid < E_) g_cnt[tid] = 0;
    float4 v = ((const float4*)(x + (size_t)t * D_))[tid];
    rs[tid] = v.x + v.y + v.z + v.w;
    rq[tid] = v.x * v.x + v.y * v.y + v.z * v.z + v.w * v.w;
    __syncthreads();
    for (int o = 128; o > 0; o >>= 1) {
        if (tid < o) { rs[tid] += rs[tid + o]; rq[tid] += rq[tid + o]; }
        __syncthreads();
    }
    float mean = rs[0] * (1.f / D_);
    float var  = rq[0] * (1.f / D_) - mean * mean;
    float inv  = rsqrtf(var + 1e-5f);
    float4 gg = ((const float4*)g)[tid];
    float4 bb = ((const float4*)b)[tid];
    float4 o4;
    o4.x = (v.x - mean) * inv * gg.x + bb.x;
    o4.y = (v.y - mean) * inv * gg.y + bb.y;
    o4.z = (v.z - mean) * inv * gg.z + bb.z;
    o4.w = (v.w - mean) * inv * gg.w + bb.w;
    if (storeF32)
        ((float4*)(g_x2 + (size_t)t * D_))[tid] = o4;
    size_t ob = (size_t)t * D_ + tid * 4;
    ((__half2*)(g_x2h + ob))[0] = __floats2half2_rn(o4.x, o4.y);
    ((__half2*)(g_x2h + ob))[1] = __floats2half2_rn(o4.z, o4.w);
}

__global__ void __launch_bounds__(256) kv_partial_kernel()
{
    __shared__ float pk[8*DK_], pv[8*DK_];
    const int bh = blockIdx.x, c = blockIdx.y;
    const int b = bh >> 4, h = bh & 15;
    const int tid = threadIdx.x;
    const int d = tid >> 2, eg = tid & 3;
    const int lr = tid >> 5;
    const int lc = (tid & 31) * 2;
    float acc[16];
    #pragma unroll
    for (int j = 0; j < 16; j++) acc[j] = 0.f;
    float ks = 0.f;
    for (int s0 = c * 256; s0 < c * 256 + 256; s0 += 8) {
        size_t base = ((size_t)(b * S_ + s0 + lr)) * D_ + h * DK_ + lc;
        *(float2*)&pk[lr * DK_ + lc] = *(const float2*)&g_k[base];
        *(float2*)&pv[lr * DK_ + lc] = *(const float2*)&g_v[base];
        __syncthreads();
        #pragma unroll
        for (int i = 0; i < 8; i++) {
            float kd = pk[i * DK_ + d];
            #pragma unroll
            for (int j = 0; j < 16; j++) acc[j] += kd * pv[i * DK_ + eg + 4 * j];
            if (eg == 0) ks += kd;
        }
        __syncthreads();
    }
    size_t ob = ((size_t)(bh * 8 + c)) * DK_ * DK_;
    #pragma unroll
    for (int j = 0; j < 16; j++) g_kvp[ob + d * DK_ + eg + 4 * j] = acc[j];
    if (eg == 0) g_ksp[(bh * 8 + c) * DK_ + d] = ks;
}

__global__ void kv_reduce_kernel()
{
    int i = blockIdx.x * 256 + threadIdx.x;
    if (i < 32 * DK_ * DK_) {
        int bh = i >> 12, r = i & 4095;
        float s = 0.f;
        #pragma unroll
        for (int c = 0; c < 8; c++) s += g_kvp[((size_t)(bh * 8 + c)) * 4096 + r];
        g_kv[i] = s;
    }
    int j = i - 32 * DK_ * DK_;
    if (j >= 0 && j < 32 * DK_) {
        int bh = j >> 6, d = j & 63;
        float s = 0.f;
        #pragma unroll
        for (int c = 0; c < 8; c++) s += g_ksp[(bh * 8 + c) * DK_ + d];
        g_ks[j] = s;
    }
}

__global__ void __launch_bounds__(256) attn_apply_kernel()
{
    __shared__ float kvs[DK_*DK_];
    __shared__ float kss[DK_];
    __shared__ float qs[64*DK_];
    const int bh = blockIdx.x;
    const int b = bh >> 4, h = bh & 15;
    const int tid = threadIdx.x;
    for (int i = tid; i < DK_ * DK_; i += 256) kvs[i] = g_kv[(size_t)bh * DK_ * DK_ + i];
    if (tid < DK_) kss[tid] = g_ks[bh * DK_ + tid];
    const int sbase = blockIdx.y * 64;
    #pragma unroll
    for (int i = 0; i < 16; i++) {
        int idx = tid + 256 * i;
        int sr = idx >> 6, dd = idx & 63;
        qs[idx] = g_q[((size_t)(b * S_ + sbase + sr)) * D_ + h * DK_ + dd];
    }
    __syncthreads();
    const int sl = tid >> 6, e = tid & 63;
    #pragma unroll 4
    for (int pass = 0; pass < 16; pass++) {
        const int srow = pass * 4 + sl;
        float acc = 0.f, qk = 0.f;
        #pragma unroll
        for (int d = 0; d < DK_; d++) {
            float qd = qs[srow * DK_ + d];
            acc += qd * kvs[d * DK_ + e];
            qk  += qd * kss[d];
        }
        g_ah[((size_t)(b * S_ + sbase + srow)) * D_ + h * DK_ + e] = __float2half(acc / (qk + 1e-6f));
    }
}

__global__ void __launch_bounds__(256) routing_kernel(
    const float* __restrict__ gw, const float* __restrict__ gb)
{
    const int lane = threadIdx.x & 31;
    const int warp = threadIdx.x >> 5;
    const int t = blockIdx.x * 8 + warp;
    const float* xr = g_x2 + (size_t)t * D_;
    float lg[8];
    #pragma unroll
    for (int e = 0; e < 8; e++) lg[e] = 0.f;
    for (int d = lane; d < D_; d += 32) {
        float xv = xr[d];
        const float4* wr = (const float4*)(gw + (size_t)d * 8);
        float4 w0 = wr[0], w1 = wr[1];
        lg[0] += xv * w0.x; lg[1] += xv * w0.y; lg[2] += xv * w0.z; lg[3] += xv * w0.w;
        lg[4] += xv * w1.x; lg[5] += xv * w1.y; lg[6] += xv * w1.z; lg[7] += xv * w1.w;
    }
    #pragma unroll
    for (int o = 16; o > 0; o >>= 1) {
        #pragma unroll
        for (int e = 0; e < 8; e++) lg[e] += __shfl_xor_sync(0xffffffffu, lg[e], o);
    }
    if (lane == 0) {
        float p[8], mx = -1e30f;
        #pragma unroll
        for (int e = 0; e < 8; e++) { lg[e] += gb[e]; mx = fmaxf(mx, lg[e]); }
        float se = 0.f;
        #pragma unroll
        for (int e = 0; e < 8; e++) { p[e] = expf(lg[e] - mx); se += p[e]; }
        int i0 = 0;
        #pragma unroll
        for (int e = 1; e < 8; e++) if (p[e] > p[i0]) i0 = e;
        int i1 = (i0 == 0) ? 1 : 0;
        #pragma unroll
        for (int e = 0; e < 8; e++) if (e != i0 && p[e] > p[i1]) i1 = e;
        float v0 = p[i0] / se, v1 = p[i1] / se;
        float inv = 1.f / (v0 + v1 + 1e-6f);
        g_topi[t*2]   = i0; g_topi[t*2+1] = i1;
        g_topw[t*2]   = v0 * inv; g_topw[t*2+1] = v1 * inv;
        atomicAdd(&g_cnt[i0], 1);
        atomicAdd(&g_cnt[i1], 1);
    }
}

__global__ void offsets_kernel()
{
    if (threadIdx.x == 0) {
        int o = 0;
        for (int e = 0; e < E_; e++) {
            g_off[e] = o;
            o += (g_cnt[e] + 127) & ~127;
            g_cur[e] = 0;
        }
        g_off[E_] = o;
    }
}

__global__ void __launch_bounds__(256) place_gather_kernel()
{
    const int slot = blockIdx.x;
    const int t = slot >> 1;
    __shared__ int row_s;
    if (threadIdx.x == 0) {
        int e = g_topi[slot];
        int pos = atomicAdd(&g_cur[e], 1);
        int row = g_off[e] + pos;
        g_row[slot] = row;
        row_s = row;
    }
    __syncthreads();
    int row = row_s;
    ((uint2*)(g_xgh + (size_t)row * D_))[threadIdx.x] =
        ((const uint2*)(g_x2h + (size_t)t * D_))[threadIdx.x];
}

__global__ void __launch_bounds__(256) combine_kernel(float* __restrict__ out)
{
    const int t = blockIdx.x;
    const int r0 = g_row[2*t], r1 = g_row[2*t+1];
    const float w0 = g_topw[2*t], w1 = g_topw[2*t+1];
    const int c = threadIdx.x;
    float4 o  = ((float4*)(out + (size_t)t * D_))[c];
    float4 y0 = ((const float4*)(g_y + (size_t)r0 * D_))[c];
    float4 y1 = ((const float4*)(g_y + (size_t)r1 * D_))[c];
    o.x += w0 * y0.x + w1 * y1.x;
    o.y += w0 * y0.y + w1 * y1.y;
    o.z += w0 * y0.z + w1 * y1.z;
    o.w += w0 * y0.w + w1 * y1.w;
    ((float4*)(out + (size_t)t * D_))[c] = o;
}

// ---------------- launch ----------------
extern "C" void kernel_launch(void* const* d_in, const int* in_sizes, int n_in,
                              void* d_out, int out_size)
{
    const float* x    = (const float*)d_in[0];
    const float* wq1  = (const float*)d_in[1];
    const float* bq1  = (const float*)d_in[2];
    const float* wq2  = (const float*)d_in[3];
    const float* bq2  = (const float*)d_in[4];
    const float* wk1  = (const float*)d_in[5];
    const float* bk1  = (const float*)d_in[6];
    const float* wk2  = (const float*)d_in[7];
    const float* bk2  = (const float*)d_in[8];
    const float* wv1  = (const float*)d_in[9];
    const float* bv1  = (const float*)d_in[10];
    const float* wv2  = (const float*)d_in[11];
    const float* bv2  = (const float*)d_in[12];
    const float* wo   = (const float*)d_in[13];
    const float* bo   = (const float*)d_in[14];
    const float* ln1g = (const float*)d_in[15];
    const float* ln1b = (const float*)d_in[16];
    const float* ln2g = (const float*)d_in[17];
    const float* ln2b = (const float*)d_in[18];
    const float* gw   = (const float*)d_in[19];
    const float* gb   = (const float*)d_in[20];
    const float* ew1  = (const float*)d_in[21];
    const float* eb1  = (const float*)d_in[22];
    const float* ew2  = (const float*)d_in[23];
    const float* eb2  = (const float*)d_in[24];
    const float* ew3  = (const float*)d_in[25];
    const float* eb3  = (const float*)d_in[26];
    float* out = (float*)d_out;

    static int s_init = 0;
    if (!s_init) {
        cudaFuncSetAttribute(mm_gated_kernel, cudaFuncAttributeMaxDynamicSharedMemorySize, SMEM_GATED);
        cudaFuncSetAttribute(mm_moeh_kernel,  cudaFuncAttributeMaxDynamicSharedMemorySize, SMEM_GATED);
        cudaFuncSetAttribute(mm_out_kernel,   cudaFuncAttributeMaxDynamicSharedMemorySize, SMEM_SINGLE);
        cudaFuncSetAttribute(mm_moey_kernel,  cudaFuncAttributeMaxDynamicSharedMemorySize, SMEM_SINGLE);
        s_init = 1;
    }

    __half *wd, *e1, *e3, *e2;
    float *qp, *kp, *vp;
    cudaGetSymbolAddress((void**)&wd, g_wd);
    cudaGetSymbolAddress((void**)&e1, g_e1);
    cudaGetSymbolAddress((void**)&e3, g_e3);
    cudaGetSymbolAddress((void**)&e2, g_e2);
    cudaGetSymbolAddress((void**)&qp, g_q);
    cudaGetSymbolAddress((void**)&kp, g_k);
    cudaGetSymbolAddress((void**)&vp, g_v);

    const size_t DD = (size_t)D_ * D_;
    const int N16_DD = (int)(DD / 16);
    const int N16_E  = (int)(8 * DD * 4 / 16);

    Ptr7 p7;
    p7.p[0] = wq1; p7.p[1] = wq2; p7.p[2] = wk1; p7.p[3] = wk2;
    p7.p[4] = wv1; p7.p[5] = wv2; p7.p[6] = wo;
    conv7_kernel<<<dim3(N16_DD / 256, 7), 256>>>(p7, wd);
    PtrE pe;
    pe.s[0] = ew1; pe.d[0] = e1;
    pe.s[1] = ew3; pe.d[1] = e3;
    pe.s[2] = ew2; pe.d[2] = e2;
    convE3_kernel<<<dim3(N16_E / 256, 3), 256>>>(pe, N16_E);

    ln_kernel<<<TOK, 256>>>(x, ln1g, ln1b, /*storeF32=*/0, /*clearCnt=*/0);

    GatedArgs ga;
    ga.w1[0] = wd + 0 * DD; ga.w2[0] = wd + 1 * DD; ga.b1[0] = bq1; ga.b2[0] = bq2; ga.C[0] = qp;
    ga.w1[1] = wd + 2 * DD; ga.w2[1] = wd + 3 * DD; ga.b1[1] = bk1; ga.b2[1] = bk2; ga.C[1] = kp;
    ga.w1[2] = wd + 4 * DD; ga.w2[2] = wd + 5 * DD; ga.b1[2] = bv1; ga.b2[2] = bv2; ga.C[2] = vp;
    mm_gated_kernel<<<dim3(TOK / 128, D_ / 64, 3), 256, SMEM_GATED>>>(ga);

    kv_partial_kernel<<<dim3(32, 8), 256>>>();
    kv_reduce_kernel<<<(32 * DK_ * DK_ + 32 * DK_ + 255) / 256, 256>>>();
    attn_apply_kernel<<<dim3(32, S_ / 64), 256>>>();
    mm_out_kernel<<<dim3(TOK / 128, D_ / 64), 256, SMEM_SINGLE>>>(wd + 6 * DD, bo, x, out);
    ln_kernel<<<TOK, 256>>>(out, ln2g, ln2b, /*storeF32=*/1, /*clearCnt=*/1);
    routing_kernel<<<TOK / 8, 256>>>(gw, gb);
    offsets_kernel<<<1, 1>>>();
    place_gather_kernel<<<TOK * 2, 256>>>();
    mm_moeh_kernel<<<dim3(CAP_ROWS / 128, F_ / 64), 256, SMEM_GATED>>>(eb1, eb3);
    mm_moey_kernel<<<dim3(CAP_ROWS / 128, D_ / 64), 256, SMEM_SINGLE>>>(eb2);
    combine_kernel<<<TOK, 256>>>(out);
}

// round 16
// speedup vs baseline: 1.0672x; 1.0672x over previous
#include <cuda_runtime.h>
#include <cuda_fp16.h>
#include <math.h>
#include <stdint.h>

#define B_   2
#define S_   2048
#define D_   1024
#define H_   16
#define DK_  64
#define F_   4096
#define E_   8
#define TOK  (B_*S_)
#define CAP_ROWS (TOK*2 + E_*128)

#define KC   32               // k per chunk (halves)
#define SROW 40               // padded halves per A smem row (80B)
#define TILE_AB (128*SROW*2)  // 10240 bytes: A tile 128x32
#define TILE_BB (32*256)      // 8192 bytes: B tile 32(k) x 128(n)
#define TILE_BB2 (32*128)     // 4096 bytes: B tile 32(k) x 64(n)
#define STG_G  (TILE_AB + 2*TILE_BB2)  // 18432 (256-thr dual, N=64)
#define STG_S  (TILE_AB + 1*TILE_BB)   // 18432 (256-thr single, N=128)
#define NSTG   4   // dual core stages
#define NSTG_S 5   // single core stages (deeper prefetch for long-K moey)

// ---------------- scratch ----------------
__device__ __align__(128) float  g_x2[TOK*D_];
__device__ __align__(128) __half g_x2h[TOK*D_];
__device__ __align__(128) float  g_q [TOK*D_];
__device__ __align__(128) float  g_k [TOK*D_];
__device__ __align__(128) float  g_v [TOK*D_];
__device__ __align__(128) __half g_ah[TOK*D_];
__device__ __align__(128) float  g_kvp[32*8*DK_*DK_];
__device__ __align__(128) float  g_kv [32*DK_*DK_];
__device__ __align__(128) float  g_ksp[32*8*DK_];
__device__ __align__(128) float  g_ks [32*DK_];
__device__ __align__(128) __half g_xgh[(size_t)CAP_ROWS*D_];
__device__ __align__(128) __half g_hh[(size_t)CAP_ROWS*F_];
__device__ __align__(128) float  g_y [(size_t)CAP_ROWS*D_];
__device__ __align__(128) __half g_wd[7*(size_t)D_*D_];
__device__ __align__(128) __half g_e1[8*(size_t)D_*F_];
__device__ __align__(128) __half g_e3[8*(size_t)D_*F_];
__device__ __align__(128) __half g_e2[8*(size_t)F_*D_];
__device__ int   g_cnt[E_];
__device__ int   g_off[E_+1];
__device__ int   g_cur[E_];
__device__ int   g_topi[TOK*2];
__device__ float g_topw[TOK*2];
__device__ int   g_row[TOK*2];

// ---------------- helpers ----------------
__device__ __forceinline__ uint32_t smem_u32(const void* p) {
    uint32_t a;
    asm("{ .reg .u64 t; cvta.to.shared.u64 t, %1; cvt.u32.u64 %0, t; }" : "=r"(a) : "l"(p));
    return a;
}
__device__ __forceinline__ float silu_gate(float a, float c) {
    return a / (1.f + expf(-a)) * c;
}
__device__ __forceinline__ float phi1(float x) { return x > 0.f ? x + 1.f : expf(x); }

__device__ __forceinline__ void cp16(uint32_t s, const void* g) {
    asm volatile("cp.async.cg.shared.global [%0], [%1], 16;" :: "r"(s), "l"(g) : "memory");
}

#define LDSM4(r, addr) \
    asm volatile("ldmatrix.sync.aligned.m8n8.x4.shared.b16 {%0,%1,%2,%3}, [%4];" \
        : "=r"((r)[0]), "=r"((r)[1]), "=r"((r)[2]), "=r"((r)[3]) : "r"(addr))
#define LDSM4T(r, addr) \
    asm volatile("ldmatrix.sync.aligned.m8n8.x4.trans.shared.b16 {%0,%1,%2,%3}, [%4];" \
        : "=r"((r)[0]), "=r"((r)[1]), "=r"((r)[2]), "=r"((r)[3]) : "r"(addr))
#define MMA_F16(c, a, b) \
    asm volatile("mma.sync.aligned.m16n8k16.row.col.f32.f16.f16.f32 " \
        "{%0,%1,%2,%3}, {%4,%5,%6,%7}, {%8,%9}, {%0,%1,%2,%3};" \
        : "+f"((c)[0]), "+f"((c)[1]), "+f"((c)[2]), "+f"((c)[3]) \
        : "r"((a)[0]), "r"((a)[1]), "r"((a)[2]), "r"((a)[3]), "r"((b)[0]), "r"((b)[1]))

// ======== DUAL 256-thread core: 128x64 tile, 2 CTA/SM ========
__device__ __forceinline__ void ld_chunk_g(
    const __half* A, int lda, const __half* B0, const __half* B1, int ldb,
    int k0, uint32_t st, int tid)
{
    const int r = tid >> 1;
    const int c = (tid & 1) * 16;
    const __half* arow = A + (size_t)r * lda + k0 + c;
    cp16(st + (uint32_t)(r * SROW + c) * 2, arow);
    cp16(st + (uint32_t)(r * SROW + c + 8) * 2, arow + 8);
    const int brow = tid >> 3;
    const int bg = tid & 7;
    const uint32_t bso = (uint32_t)brow * 128 + (uint32_t)((bg ^ (brow & 7)) << 4);
    const size_t go = (size_t)(k0 + brow) * ldb + bg * 8;
    cp16(st + TILE_AB + bso, B0 + go);
    cp16(st + TILE_AB + TILE_BB2 + bso, B1 + go);
}

__device__ __forceinline__ void compute_chunk_g(
    uint32_t st, float (&acc0)[4][2][4], float (&acc1)[4][2][4],
    int wm, int wn, int lane)
{
    const uint32_t aoff = (uint32_t)(((lane & 7) + ((lane >> 3) & 1) * 8) * SROW + (lane >> 4) * 8) * 2;
    const uint32_t stB0 = st + TILE_AB;
    const uint32_t stB1 = st + TILE_AB + TILE_BB2;
    const uint32_t bbase = (uint32_t)lane * 128;
    const uint32_t kx = (uint32_t)(lane & 7) << 4;
    uint32_t b0[2][4], b1[2][4];
    #pragma unroll
    for (int nt = 0; nt < 2; nt++) {
        const uint32_t gy = ((uint32_t)(wn * 2 + nt) << 4) ^ kx;
        LDSM4T(b0[nt], stB0 + bbase + gy);
        LDSM4T(b1[nt], stB1 + bbase + gy);
    }
    #pragma unroll
    for (int ks = 0; ks < 2; ks++) {
        uint32_t a[4][4];
        #pragma unroll
        for (int mt = 0; mt < 4; mt++) {
            uint32_t addr = st + (uint32_t)((wm * 64 + mt * 16) * SROW + ks * 16) * 2 + aoff;
            LDSM4(a[mt], addr);
        }
        #pragma unroll
        for (int mt = 0; mt < 4; mt++) {
            #pragma unroll
            for (int nt = 0; nt < 2; nt++) {
                MMA_F16(acc0[mt][nt], a[mt], (b0[nt] + 2 * ks));
                MMA_F16(acc1[mt][nt], a[mt], (b1[nt] + 2 * ks));
            }
        }
    }
}

__device__ __forceinline__ void mma_mainloop_g(
    const __half* A, int lda, const __half* B0, const __half* B1, int ldb,
    int K, uint32_t sm, float (&acc0)[4][2][4], float (&acc1)[4][2][4])
{
    const int tid = threadIdx.x;
    const int lane = tid & 31, wid = tid >> 5;
    const int wm = wid & 1, wn = wid >> 1;
    const int NC = K / KC;
    #pragma unroll
    for (int p = 0; p < NSTG - 1; p++) {
        ld_chunk_g(A, lda, B0, B1, ldb, p * KC, sm + (uint32_t)p * STG_G, tid);
        asm volatile("cp.async.commit_group;" ::: "memory");
    }
    for (int k = 0; k < NC; k++) {
        asm volatile("cp.async.wait_group 2;" ::: "memory");
        __syncthreads();
        if (k + NSTG - 1 < NC)
            ld_chunk_g(A, lda, B0, B1, ldb, (k + NSTG - 1) * KC,
                       sm + (uint32_t)((k + NSTG - 1) & (NSTG - 1)) * STG_G, tid);
        asm volatile("cp.async.commit_group;" ::: "memory");
        compute_chunk_g(sm + (uint32_t)(k & (NSTG - 1)) * STG_G, acc0, acc1, wm, wn, lane);
    }
}

// ======== SINGLE 256-thread core: 128x128 tile, 2 CTA/SM, 5-stage ========
__device__ __forceinline__ void ld_chunk_s(
    const __half* A, int lda, const __half* B, int ldb,
    int k0, uint32_t st, int tid)
{
    const int r = tid >> 1;
    const int c = (tid & 1) * 16;
    const __half* arow = A + (size_t)r * lda + k0 + c;
    cp16(st + (uint32_t)(r * SROW + c) * 2, arow);
    cp16(st + (uint32_t)(r * SROW + c + 8) * 2, arow + 8);
    #pragma unroll
    for (int hh = 0; hh < 2; hh++) {
        const int idx = tid + hh * 256;
        const int row = idx >> 4;
        const int bg = idx & 15;
        const uint32_t bso = (uint32_t)row * 256 + (uint32_t)((bg ^ (row & 7)) << 4);
        cp16(st + TILE_AB + bso, B + (size_t)(k0 + row) * ldb + bg * 8);
    }
}

// 8 warps as 2(m) x 4(n); warp tile 64x32 (mt=4, nt=4)
__device__ __forceinline__ void compute_chunk_s(
    uint32_t st, float (&acc)[4][4][4], int wm, int wn, int lane)
{
    const uint32_t aoff = (uint32_t)(((lane & 7) + ((lane >> 3) & 1) * 8) * SROW + (lane >> 4) * 8) * 2;
    const uint32_t stB = st + TILE_AB;
    const uint32_t bbase = (uint32_t)lane * 256;
    const uint32_t kx = (uint32_t)(lane & 7) << 4;
    uint32_t b[4][4];
    #pragma unroll
    for (int nt = 0; nt < 4; nt++) {
        const uint32_t gy = ((uint32_t)(wn * 4 + nt) << 4) ^ kx;
        LDSM4T(b[nt], stB + bbase + gy);
    }
    #pragma unroll
    for (int ks = 0; ks < 2; ks++) {
        uint32_t a[4][4];
        #pragma unroll
        for (int mt = 0; mt < 4; mt++) {
            uint32_t addr = st + (uint32_t)((wm * 64 + mt * 16) * SROW + ks * 16) * 2 + aoff;
            LDSM4(a[mt], addr);
        }
        #pragma unroll
        for (int mt = 0; mt < 4; mt++) {
            #pragma unroll
            for (int nt = 0; nt < 4; nt++) {
                MMA_F16(acc[mt][nt], a[mt], (b[nt] + 2 * ks));
            }
        }
    }
}

__device__ __forceinline__ void mma_mainloop_s(
    const __half* A, int lda, const __half* B, int ldb,
    int K, uint32_t sm, float (&acc)[4][4][4])
{
    const int tid = threadIdx.x;
    const int lane = tid & 31, wid = tid >> 5;
    const int wm = wid & 1, wn = wid >> 1;
    const int NC = K / KC;
    #pragma unroll
    for (int p = 0; p < NSTG_S - 1; p++) {
        ld_chunk_s(A, lda, B, ldb, p * KC, sm + (uint32_t)p * STG_S, tid);
        asm volatile("cp.async.commit_group;" ::: "memory");
    }
    int sld = NSTG_S - 1, scp = 0;
    for (int k = 0; k < NC; k++) {
        asm volatile("cp.async.wait_group 3;" ::: "memory");
        __syncthreads();
        if (k + NSTG_S - 1 < NC)
            ld_chunk_s(A, lda, B, ldb, (k + NSTG_S - 1) * KC,
                       sm + (uint32_t)sld * STG_S, tid);
        asm volatile("cp.async.commit_group;" ::: "memory");
        compute_chunk_s(sm + (uint32_t)scp * STG_S, acc, wm, wn, lane);
        sld = (sld == NSTG_S - 1) ? 0 : sld + 1;
        scp = (scp == NSTG_S - 1) ? 0 : scp + 1;
    }
}

// ---------------- GEMM kernels ----------------
#define SMEM_GATED  (NSTG*STG_G)     // 73728
#define SMEM_SINGLE (NSTG_S*STG_S)   // 92160

struct GatedArgs {
    const __half* w1[3];
    const __half* w2[3];
    const float*  b1[3];
    const float*  b2[3];
    float*        C [3];
};

// z in {0,1,2}: q(phi), k(phi), v(no phi)
__global__ void __launch_bounds__(256, 2) mm_gated_kernel(GatedArgs ga)
{
    extern __shared__ __align__(128) char smem[];
    uint32_t sm = smem_u32(smem);
    const int z = blockIdx.z;
    const int bm0 = blockIdx.x * 128, bn0 = blockIdx.y * 64;
    float acc0[4][2][4] = {}, acc1[4][2][4] = {};
    mma_mainloop_g(g_x2h + (size_t)bm0 * D_, D_,
                   ga.w1[z] + bn0, ga.w2[z] + bn0, D_,
                   D_, sm, acc0, acc1);
    const float* bias1 = ga.b1[z];
    const float* bias2 = ga.b2[z];
    float* C = ga.C[z];
    const int applyPhi = (z != 2);
    const int lane = threadIdx.x & 31, wid = threadIdx.x >> 5;
    const int wm = wid & 1, wn = wid >> 1;
    const int quad = lane >> 2, tq = lane & 3;
    #pragma unroll
    for (int mt = 0; mt < 4; mt++) {
        #pragma unroll
        for (int nt = 0; nt < 2; nt++) {
            const int col = bn0 + wn * 16 + nt * 8 + tq * 2;
            const int r0 = bm0 + wm * 64 + mt * 16 + quad;
            float2 bb1 = *(const float2*)(bias1 + col);
            float2 bb2 = *(const float2*)(bias2 + col);
            float2 v;
            v.x = silu_gate(acc0[mt][nt][0] + bb1.x, acc1[mt][nt][0] + bb2.x);
            v.y = silu_gate(acc0[mt][nt][1] + bb1.y, acc1[mt][nt][1] + bb2.y);
            if (applyPhi) { v.x = phi1(v.x); v.y = phi1(v.y); }
            *(float2*)(C + (size_t)r0 * D_ + col) = v;
            v.x = silu_gate(acc0[mt][nt][2] + bb1.x, acc1[mt][nt][2] + bb2.x);
            v.y = silu_gate(acc0[mt][nt][3] + bb1.y, acc1[mt][nt][3] + bb2.y);
            if (applyPhi) { v.x = phi1(v.x); v.y = phi1(v.y); }
            *(float2*)(C + (size_t)(r0 + 8) * D_ + col) = v;
        }
    }
}

// out = attn @ wo + bo + residual  (single 128x128, 2 CTAs/SM)
__global__ void __launch_bounds__(256, 2) mm_out_kernel(
    const __half* __restrict__ w, const float* __restrict__ bias,
    const float* __restrict__ res, float* __restrict__ C)
{
    extern __shared__ __align__(128) char smem[];
    uint32_t sm = smem_u32(smem);
    const int bm0 = blockIdx.x * 128, bn0 = blockIdx.y * 128;
    float acc[4][4][4] = {};
    mma_mainloop_s(g_ah + (size_t)bm0 * D_, D_, w + bn0, D_, D_, sm, acc);
    const int lane = threadIdx.x & 31, wid = threadIdx.x >> 5;
    const int wm = wid & 1, wn = wid >> 1;
    const int quad = lane >> 2, tq = lane & 3;
    #pragma unroll
    for (int mt = 0; mt < 4; mt++) {
        #pragma unroll
        for (int nt = 0; nt < 4; nt++) {
            const int col = bn0 + wn * 32 + nt * 8 + tq * 2;
            const int r0 = bm0 + wm * 64 + mt * 16 + quad;
            float2 bb = *(const float2*)(bias + col);
            float2 rr0 = *(const float2*)(res + (size_t)r0 * D_ + col);
            float2 rr1 = *(const float2*)(res + (size_t)(r0 + 8) * D_ + col);
            float2 v;
            v.x = acc[mt][nt][0] + bb.x + rr0.x;
            v.y = acc[mt][nt][1] + bb.y + rr0.y;
            *(float2*)(C + (size_t)r0 * D_ + col) = v;
            v.x = acc[mt][nt][2] + bb.x + rr1.x;
            v.y = acc[mt][nt][3] + bb.y + rr1.y;
            *(float2*)(C + (size_t)(r0 + 8) * D_ + col) = v;
        }
    }
}

// h = silu(xg@w1[e]+b1[e]) * (xg@w3[e]+b3[e])  (dual, N=64, 2 CTAs/SM)
__global__ void __launch_bounds__(256, 2) mm_moeh_kernel(
    const float* __restrict__ eb1, const float* __restrict__ eb3)
{
    const int bm0 = blockIdx.x * 128;
    if (bm0 >= g_off[E_]) return;
    int e = 0;
    #pragma unroll
    for (int i = 0; i < E_; i++) if (bm0 >= g_off[i + 1]) e = i + 1;
    extern __shared__ __align__(128) char smem[];
    uint32_t sm = smem_u32(smem);
    const int bn0 = blockIdx.y * 64;
    const size_t wb = (size_t)e * D_ * F_ + bn0;
    float acc0[4][2][4] = {}, acc1[4][2][4] = {};
    mma_mainloop_g(g_xgh + (size_t)bm0 * D_, D_, g_e1 + wb, g_e3 + wb, F_,
                   D_, sm, acc0, acc1);
    const int lane = threadIdx.x & 31, wid = threadIdx.x >> 5;
    const int wm = wid & 1, wn = wid >> 1;
    const int quad = lane >> 2, tq = lane & 3;
    const float* b1 = eb1 + (size_t)e * F_;
    const float* b3 = eb3 + (size_t)e * F_;
    #pragma unroll
    for (int mt = 0; mt < 4; mt++) {
        #pragma unroll
        for (int nt = 0; nt < 2; nt++) {
            const int col = bn0 + wn * 16 + nt * 8 + tq * 2;
            const int r0 = bm0 + wm * 64 + mt * 16 + quad;
            float2 bb1 = *(const float2*)(b1 + col);
            float2 bb3 = *(const float2*)(b3 + col);
            float v0 = silu_gate(acc0[mt][nt][0] + bb1.x, acc1[mt][nt][0] + bb3.x);
            float v1 = silu_gate(acc0[mt][nt][1] + bb1.y, acc1[mt][nt][1] + bb3.y);
            *(__half2*)(g_hh + (size_t)r0 * F_ + col) = __floats2half2_rn(v0, v1);
            v0 = silu_gate(acc0[mt][nt][2] + bb1.x, acc1[mt][nt][2] + bb3.x);
            v1 = silu_gate(acc0[mt][nt][3] + bb1.y, acc1[mt][nt][3] + bb3.y);
            *(__half2*)(g_hh + (size_t)(r0 + 8) * F_ + col) = __floats2half2_rn(v0, v1);
        }
    }
}

// y = h @ w2[e] + b2[e]  (single 128x128, 2 CTAs/SM)
__global__ void __launch_bounds__(256, 2) mm_moey_kernel(const float* __restrict__ eb2)
{
    const int bm0 = blockIdx.x * 128;
    if (bm0 >= g_off[E_]) return;
    int e = 0;
    #pragma unroll
    for (int i = 0; i < E_; i++) if (bm0 >= g_off[i + 1]) e = i + 1;
    extern __shared__ __align__(128) char smem[];
    uint32_t sm = smem_u32(smem);
    const int bn0 = blockIdx.y * 128;
    const size_t wb = (size_t)e * F_ * D_ + bn0;
    float acc[4][4][4] = {};
    mma_mainloop_s(g_hh + (size_t)bm0 * F_, F_, g_e2 + wb, D_, F_, sm, acc);
    const int lane = threadIdx.x & 31, wid = threadIdx.x >> 5;
    const int wm = wid & 1, wn = wid >> 1;
    const int quad = lane >> 2, tq = lane & 3;
    const float* b2 = eb2 + (size_t)e * D_;
    #pragma unroll
    for (int mt = 0; mt < 4; mt++) {
        #pragma unroll
        for (int nt = 0; nt < 4; nt++) {
            const int col = bn0 + wn * 32 + nt * 8 + tq * 2;
            const int r0 = bm0 + wm * 64 + mt * 16 + quad;
            float2 bb = *(const float2*)(b2 + col);
            float2 v;
            v.x = acc[mt][nt][0] + bb.x;
            v.y = acc[mt][nt][1] + bb.y;
            *(float2*)(g_y + (size_t)r0 * D_ + col) = v;
            v.x = acc[mt][nt][2] + bb.x;
            v.y = acc[mt][nt][3] + bb.y;
            *(float2*)(g_y + (size_t)(r0 + 8) * D_ + col) = v;
        }
    }
}

// ---------------- conversion: streaming fp32 -> fp16, 16 elems/thread ----------------
__device__ __forceinline__ void conv16(const float* S, __half* Dst, int i)
{
    #pragma unroll
    for (int h = 0; h < 2; h++) {
        float4 a = ((const float4*)S)[4 * i + 2 * h];
        float4 b = ((const float4*)S)[4 * i + 2 * h + 1];
        __half2 h0 = __floats2half2_rn(a.x, a.y);
        __half2 h1 = __floats2half2_rn(a.z, a.w);
        __half2 h2 = __floats2half2_rn(b.x, b.y);
        __half2 h3 = __floats2half2_rn(b.z, b.w);
        uint4 o;
        o.x = *(uint32_t*)&h0; o.y = *(uint32_t*)&h1;
        o.z = *(uint32_t*)&h2; o.w = *(uint32_t*)&h3;
        ((uint4*)Dst)[2 * i + h] = o;
    }
}

struct Ptr7 { const float* p[7]; };
__global__ void __launch_bounds__(256) conv7_kernel(Ptr7 src, __half* dst)
{
    const int m = blockIdx.y;
    const int n16 = (int)((size_t)D_ * D_ / 16);
    int i = blockIdx.x * 256 + threadIdx.x;
    if (i < n16) conv16(src.p[m], dst + (size_t)m * D_ * D_, i);
}

struct PtrE { const float* s[3]; __half* d[3]; };
__global__ void __launch_bounds__(256) convE3_kernel(PtrE pe, int n16)
{
    const int m = blockIdx.y;
    int i = blockIdx.x * 256 + threadIdx.x;
    if (i < n16) conv16(pe.s[m], pe.d[m], i);
}

// ---------------- non-GEMM kernels ----------------
__global__ void __launch_bounds__(256) ln_kernel(
    const float* __restrict__ x, const float* __restrict__ g, const float* __restrict__ b,
    int storeF32, int clearCnt)
{
    __shared__ float rs[256], rq[256];
    const int t = blockIdx.x, tid = threadIdx.x;
    if (clearCnt && t == 0 && tid < E_) g_cnt[tid] = 0;
    float4 v = ((const float4*)(x + (size_t)t * D_))[tid];
    rs[tid] = v.x + v.y + v.z + v.w;
    rq[tid] = v.x * v.x + v.y * v.y + v.z * v.z + v.w * v.w;
    __syncthreads();
    for (int o = 128; o > 0; o >>= 1) {
        if (tid < o) { rs[tid] += rs[tid + o]; rq[tid] += rq[tid + o]; }
        __syncthreads();
    }
    float mean = rs[0] * (1.f / D_);
    float var  = rq[0] * (1.f / D_) - mean * mean;
    float inv  = rsqrtf(var + 1e-5f);
    float4 gg = ((const float4*)g)[tid];
    float4 bb = ((const float4*)b)[tid];
    float4 o4;
    o4.x = (v.x - mean) * inv * gg.x + bb.x;
    o4.y = (v.y - mean) * inv * gg.y + bb.y;
    o4.z = (v.z - mean) * inv * gg.z + bb.z;
    o4.w = (v.w - mean) * inv * gg.w + bb.w;
    if (storeF32)
        ((float4*)(g_x2 + (size_t)t * D_))[tid] = o4;
    size_t ob = (size_t)t * D_ + tid * 4;
    ((__half2*)(g_x2h + ob))[0] = __floats2half2_rn(o4.x, o4.y);
    ((__half2*)(g_x2h + ob))[1] = __floats2half2_rn(o4.z, o4.w);
}

__global__ void __launch_bounds__(256) kv_partial_kernel()
{
    __shared__ float pk[8*DK_], pv[8*DK_];
    const int bh = blockIdx.x, c = blockIdx.y;
    const int b = bh >> 4, h = bh & 15;
    const int tid = threadIdx.x;
    const int d = tid >> 2, eg = tid & 3;
    const int lr = tid >> 5;
    const int lc = (tid & 31) * 2;
    float acc[16];
    #pragma unroll
    for (int j = 0; j < 16; j++) acc[j] = 0.f;
    float ks = 0.f;
    for (int s0 = c * 256; s0 < c * 256 + 256; s0 += 8) {
        size_t base = ((size_t)(b * S_ + s0 + lr)) * D_ + h * DK_ + lc;
        *(float2*)&pk[lr * DK_ + lc] = *(const float2*)&g_k[base];
        *(float2*)&pv[lr * DK_ + lc] = *(const float2*)&g_v[base];
        __syncthreads();
        #pragma unroll
        for (int i = 0; i < 8; i++) {
            float kd = pk[i * DK_ + d];
            #pragma unroll
            for (int j = 0; j < 16; j++) acc[j] += kd * pv[i * DK_ + eg + 4 * j];
            if (eg == 0) ks += kd;
        }
        __syncthreads();
    }
    size_t ob = ((size_t)(bh * 8 + c)) * DK_ * DK_;
    #pragma unroll
    for (int j = 0; j < 16; j++) g_kvp[ob + d * DK_ + eg + 4 * j] = acc[j];
    if (eg == 0) g_ksp[(bh * 8 + c) * DK_ + d] = ks;
}

__global__ void kv_reduce_kernel()
{
    int i = blockIdx.x * 256 + threadIdx.x;
    if (i < 32 * DK_ * DK_) {
        int bh = i >> 12, r = i & 4095;
        float s = 0.f;
        #pragma unroll
        for (int c = 0; c < 8; c++) s += g_kvp[((size_t)(bh * 8 + c)) * 4096 + r];
        g_kv[i] = s;
    }
    int j = i - 32 * DK_ * DK_;
    if (j >= 0 && j < 32 * DK_) {
        int bh = j >> 6, d = j & 63;
        float s = 0.f;
        #pragma unroll
        for (int c = 0; c < 8; c++) s += g_ksp[(bh * 8 + c) * DK_ + d];
        g_ks[j] = s;
    }
}

__global__ void __launch_bounds__(256) attn_apply_kernel()
{
    __shared__ float kvs[DK_*DK_];
    __shared__ float kss[DK_];
    __shared__ float qs[64*DK_];
    const int bh = blockIdx.x;
    const int b = bh >> 4, h = bh & 15;
    const int tid = threadIdx.x;
    for (int i = tid; i < DK_ * DK_; i += 256) kvs[i] = g_kv[(size_t)bh * DK_ * DK_ + i];
    if (tid < DK_) kss[tid] = g_ks[bh * DK_ + tid];
    const int sbase = blockIdx.y * 64;
    #pragma unroll
    for (int i = 0; i < 16; i++) {
        int idx = tid + 256 * i;
        int sr = idx >> 6, dd = idx & 63;
        qs[idx] = g_q[((size_t)(b * S_ + sbase + sr)) * D_ + h * DK_ + dd];
    }
    __syncthreads();
    const int sl = tid >> 6, e = tid & 63;
    #pragma unroll 4
    for (int pass = 0; pass < 16; pass++) {
        const int srow = pass * 4 + sl;
        float acc = 0.f, qk = 0.f;
        #pragma unroll
        for (int d = 0; d < DK_; d++) {
            float qd = qs[srow * DK_ + d];
            acc += qd * kvs[d * DK_ + e];
            qk  += qd * kss[d];
        }
        g_ah[((size_t)(b * S_ + sbase + srow)) * D_ + h * DK_ + e] = __float2half(acc / (qk + 1e-6f));
    }
}

__global__ void __launch_bounds__(256) routing_kernel(
    const float* __restrict__ gw, const float* __restrict__ gb)
{
    const int lane = threadIdx.x & 31;
    const int warp = threadIdx.x >> 5;
    const int t = blockIdx.x * 8 + warp;
    const float* xr = g_x2 + (size_t)t * D_;
    float lg[8];
    #pragma unroll
    for (int e = 0; e < 8; e++) lg[e] = 0.f;
    for (int d = lane; d < D_; d += 32) {
        float xv = xr[d];
        const float4* wr = (const float4*)(gw + (size_t)d * 8);
        float4 w0 = wr[0], w1 = wr[1];
        lg[0] += xv * w0.x; lg[1] += xv * w0.y; lg[2] += xv * w0.z; lg[3] += xv * w0.w;
        lg[4] += xv * w1.x; lg[5] += xv * w1.y; lg[6] += xv * w1.z; lg[7] += xv * w1.w;
    }
    #pragma unroll
    for (int o = 16; o > 0; o >>= 1) {
        #pragma unroll
        for (int e = 0; e < 8; e++) lg[e] += __shfl_xor_sync(0xffffffffu, lg[e], o);
    }
    if (lane == 0) {
        float p[8], mx = -1e30f;
        #pragma unroll
        for (int e = 0; e < 8; e++) { lg[e] += gb[e]; mx = fmaxf(mx, lg[e]); }
        float se = 0.f;
        #pragma unroll
        for (int e = 0; e < 8; e++) { p[e] = expf(lg[e] - mx); se += p[e]; }
        int i0 = 0;
        #pragma unroll
        for (int e = 1; e < 8; e++) if (p[e] > p[i0]) i0 = e;
        int i1 = (i0 == 0) ? 1 : 0;
        #pragma unroll
        for (int e = 0; e < 8; e++) if (e != i0 && p[e] > p[i1]) i1 = e;
        float v0 = p[i0] / se, v1 = p[i1] / se;
        float inv = 1.f / (v0 + v1 + 1e-6f);
        g_topi[t*2]   = i0; g_topi[t*2+1] = i1;
        g_topw[t*2]   = v0 * inv; g_topw[t*2+1] = v1 * inv;
        atomicAdd(&g_cnt[i0], 1);
        atomicAdd(&g_cnt[i1], 1);
    }
}

__global__ void offsets_kernel()
{
    if (threadIdx.x == 0) {
        int o = 0;
        for (int e = 0; e < E_; e++) {
            g_off[e] = o;
            o += (g_cnt[e] + 127) & ~127;
            g_cur[e] = 0;
        }
        g_off[E_] = o;
    }
}

__global__ void __launch_bounds__(256) place_gather_kernel()
{
    const int slot = blockIdx.x;
    const int t = slot >> 1;
    __shared__ int row_s;
    if (threadIdx.x == 0) {
        int e = g_topi[slot];
        int pos = atomicAdd(&g_cur[e], 1);
        int row = g_off[e] + pos;
        g_row[slot] = row;
        row_s = row;
    }
    __syncthreads();
    int row = row_s;
    ((uint2*)(g_xgh + (size_t)row * D_))[threadIdx.x] =
        ((const uint2*)(g_x2h + (size_t)t * D_))[threadIdx.x];
}

__global__ void __launch_bounds__(256) combine_kernel(float* __restrict__ out)
{
    const int t = blockIdx.x;
    const int r0 = g_row[2*t], r1 = g_row[2*t+1];
    const float w0 = g_topw[2*t], w1 = g_topw[2*t+1];
    const int c = threadIdx.x;
    float4 o  = ((float4*)(out + (size_t)t * D_))[c];
    float4 y0 = ((const float4*)(g_y + (size_t)r0 * D_))[c];
    float4 y1 = ((const float4*)(g_y + (size_t)r1 * D_))[c];
    o.x += w0 * y0.x + w1 * y1.x;
    o.y += w0 * y0.y + w1 * y1.y;
    o.z += w0 * y0.z + w1 * y1.z;
    o.w += w0 * y0.w + w1 * y1.w;
    ((float4*)(out + (size_t)t * D_))[c] = o;
}

// ---------------- launch ----------------
extern "C" void kernel_launch(void* const* d_in, const int* in_sizes, int n_in,
                              void* d_out, int out_size)
{
    const float* x    = (const float*)d_in[0];
    const float* wq1  = (const float*)d_in[1];
    const float* bq1  = (const float*)d_in[2];
    const float* wq2  = (const float*)d_in[3];
    const float* bq2  = (const float*)d_in[4];
    const float* wk1  = (const float*)d_in[5];
    const float* bk1  = (const float*)d_in[6];
    const float* wk2  = (const float*)d_in[7];
    const float* bk2  = (const float*)d_in[8];
    const float* wv1  = (const float*)d_in[9];
    const float* bv1  = (const float*)d_in[10];
    const float* wv2  = (const float*)d_in[11];
    const float* bv2  = (const float*)d_in[12];
    const float* wo   = (const float*)d_in[13];
    const float* bo   = (const float*)d_in[14];
    const float* ln1g = (const float*)d_in[15];
    const float* ln1b = (const float*)d_in[16];
    const float* ln2g = (const float*)d_in[17];
    const float* ln2b = (const float*)d_in[18];
    const float* gw   = (const float*)d_in[19];
    const float* gb   = (const float*)d_in[20];
    const float* ew1  = (const float*)d_in[21];
    const float* eb1  = (const float*)d_in[22];
    const float* ew2  = (const float*)d_in[23];
    const float* eb2  = (const float*)d_in[24];
    const float* ew3  = (const float*)d_in[25];
    const float* eb3  = (const float*)d_in[26];
    float* out = (float*)d_out;

    static int s_init = 0;
    if (!s_init) {
        cudaFuncSetAttribute(mm_gated_kernel, cudaFuncAttributeMaxDynamicSharedMemorySize, SMEM_GATED);
        cudaFuncSetAttribute(mm_moeh_kernel,  cudaFuncAttributeMaxDynamicSharedMemorySize, SMEM_GATED);
        cudaFuncSetAttribute(mm_out_kernel,   cudaFuncAttributeMaxDynamicSharedMemorySize, SMEM_SINGLE);
        cudaFuncSetAttribute(mm_moey_kernel,  cudaFuncAttributeMaxDynamicSharedMemorySize, SMEM_SINGLE);
        s_init = 1;
    }

    __half *wd, *e1, *e3, *e2;
    float *qp, *kp, *vp;
    cudaGetSymbolAddress((void**)&wd, g_wd);
    cudaGetSymbolAddress((void**)&e1, g_e1);
    cudaGetSymbolAddress((void**)&e3, g_e3);
    cudaGetSymbolAddress((void**)&e2, g_e2);
    cudaGetSymbolAddress((void**)&qp, g_q);
    cudaGetSymbolAddress((void**)&kp, g_k);
    cudaGetSymbolAddress((void**)&vp, g_v);

    const size_t DD = (size_t)D_ * D_;
    const int N16_DD = (int)(DD / 16);
    const int N16_E  = (int)(8 * DD * 4 / 16);

    Ptr7 p7;
    p7.p[0] = wq1; p7.p[1] = wq2; p7.p[2] = wk1; p7.p[3] = wk2;
    p7.p[4] = wv1; p7.p[5] = wv2; p7.p[6] = wo;
    conv7_kernel<<<dim3(N16_DD / 256, 7), 256>>>(p7, wd);
    PtrE pe;
    pe.s[0] = ew1; pe.d[0] = e1;
    pe.s[1] = ew3; pe.d[1] = e3;
    pe.s[2] = ew2; pe.d[2] = e2;
    convE3_kernel<<<dim3(N16_E / 256, 3), 256>>>(pe, N16_E);

    ln_kernel<<<TOK, 256>>>(x, ln1g, ln1b, /*storeF32=*/0, /*clearCnt=*/0);

    GatedArgs ga;
    ga.w1[0] = wd + 0 * DD; ga.w2[0] = wd + 1 * DD; ga.b1[0] = bq1; ga.b2[0] = bq2; ga.C[0] = qp;
    ga.w1[1] = wd + 2 * DD; ga.w2[1] = wd + 3 * DD; ga.b1[1] = bk1; ga.b2[1] = bk2; ga.C[1] = kp;
    ga.w1[2] = wd + 4 * DD; ga.w2[2] = wd + 5 * DD; ga.b1[2] = bv1; ga.b2[2] = bv2; ga.C[2] = vp;
    mm_gated_kernel<<<dim3(TOK / 128, D_ / 64, 3), 256, SMEM_GATED>>>(ga);

    kv_partial_kernel<<<dim3(32, 8), 256>>>();
    kv_reduce_kernel<<<(32 * DK_ * DK_ + 32 * DK_ + 255) / 256, 256>>>();
    attn_apply_kernel<<<dim3(32, S_ / 64), 256>>>();
    mm_out_kernel<<<dim3(TOK / 128, D_ / 128), 256, SMEM_SINGLE>>>(wd + 6 * DD, bo, x, out);
    ln_kernel<<<TOK, 256>>>(out, ln2g, ln2b, /*storeF32=*/1, /*clearCnt=*/1);
    routing_kernel<<<TOK / 8, 256>>>(gw, gb);
    offsets_kernel<<<1, 1>>>();
    place_gather_kernel<<<TOK * 2, 256>>>();
    mm_moeh_kernel<<<dim3(CAP_ROWS / 128, F_ / 64), 256, SMEM_GATED>>>(eb1, eb3);
    mm_moey_kernel<<<dim3(CAP_ROWS / 128, D_ / 128), 256, SMEM_SINGLE>>>(eb2);
    combine_kernel<<<TOK, 256>>>(out);
}